// round 5
// baseline (speedup 1.0000x reference)
#include <cuda_runtime.h>
#include <cuda_fp16.h>
#include <cstdint>

// ---------------- problem constants ----------------
#define BB    4
#define NQ    384
#define NK    384
#define DE    64
#define DMSG  64
#define DFF   256
#define DOUT  64
#define DINV  256

#define TQ    16
#define TK    8
#define TM    128          // pairs per tile
#define NTILES (BB * (NQ/TQ) * (NK/TK))   // 4608

#define LDA   136          // half pitch, k=128 + 8 pad
#define LDW2  264          // half pitch, k=256 + 8 pad
#define LDH   72           // half pitch, k=64 + 8 pad
#define LDAQ  260          // float pitch for sAq/sAk (bank-conflict-free)

#define NPRE  (BB * (NQ + NK))   // 3072 prelude blocks
#define NPREP 96                 // weight-prep blocks appended

// ---------------- device scratch ----------------
__device__ float g_Aq[BB * NQ * DFF];
__device__ float g_Ak[BB * NK * DFF];
__device__ __align__(16) __half g_W1T[DFF * LDA];    // [n=256][pitch 136]
__device__ __align__(16) __half g_W2T[DOUT * LDW2];  // [n=64][pitch 264]

// ---------------- SMEM map (bytes) ----------------
#define OFF_SA   0         // 128*136*2 = 34816
#define OFF_AQ   34816     // 16*260*4  = 16640
#define OFF_AK   51456     //  8*260*4  =  8320
#define OFF_W1   59776     // 256*136*2 = 69632
#define OFF_W2   129408    // 64*264*2  = 33792
#define OFF_H    163200    // 128*72*2  = 18432 (aliased: equi staging)
#define OFF_B2   181632    // 256
#define SMEM_BYTES 181888

__device__ __forceinline__ uint32_t smem_u32(const void* p) {
    uint32_t a;
    asm("{ .reg .u64 t; cvta.to.shared.u64 t, %1; cvt.u32.u64 %0, t; }" : "=r"(a) : "l"(p));
    return a;
}
__device__ __forceinline__ void ldsm4(uint32_t& r0, uint32_t& r1, uint32_t& r2, uint32_t& r3,
                                      uint32_t addr) {
    asm volatile("ldmatrix.sync.aligned.m8n8.x4.shared.b16 {%0,%1,%2,%3}, [%4];"
        : "=r"(r0), "=r"(r1), "=r"(r2), "=r"(r3) : "r"(addr));
}
__device__ __forceinline__ void mma16816(float* c, uint32_t a0, uint32_t a1, uint32_t a2,
                                         uint32_t a3, uint32_t b0, uint32_t b1) {
    asm volatile(
        "mma.sync.aligned.m16n8k16.row.col.f32.f16.f16.f32 "
        "{%0,%1,%2,%3}, {%4,%5,%6,%7}, {%8,%9}, {%0,%1,%2,%3};"
        : "+f"(c[0]), "+f"(c[1]), "+f"(c[2]), "+f"(c[3])
        : "r"(a0), "r"(a1), "r"(a2), "r"(a3), "r"(b0), "r"(b1));
}
__device__ __forceinline__ float silu_f(float x) {
    return x * (1.f / (1.f + __expf(-x)));
}

// ---------------- prelude: A_q / A_k (+ appended weight-prep) ----------------
__global__ void __launch_bounds__(256) prelude_kernel(
    const float* __restrict__ q_inv, const float* __restrict__ k_inv,
    const float* __restrict__ Wq, const float* __restrict__ bq,
    const float* __restrict__ Wk, const float* __restrict__ bk,
    const float* __restrict__ W1, const float* __restrict__ b1,
    const float* __restrict__ W2)
{
    int blk = blockIdx.x;

    if (blk >= NPRE) {
        int idx = (blk - NPRE) * 256 + threadIdx.x;
        int total = DFF * 128 + DOUT * DFF;
        for (; idx < total; idx += NPREP * 256) {
            if (idx < DFF * 128) {
                int n = idx >> 7, k = idx & 127;              // W1T[n,k] = W1[128+k, n]
                g_W1T[n * LDA + k] = __float2half(W1[(128 + k) * DFF + n]);
            } else {
                int j = idx - DFF * 128;
                int n = j >> 8, k = j & 255;                  // W2T[n,k] = W2[k, n]
                g_W2T[n * LDW2 + k] = __float2half(W2[k * DOUT + n]);
            }
        }
        return;
    }

    bool isQ = blk < BB * NQ;
    int bn = isQ ? blk : blk - BB * NQ;

    const float* inv  = isQ ? (q_inv + bn * DINV) : (k_inv + bn * DINV);
    const float* W    = isQ ? Wq : Wk;
    const float* bias = isQ ? bq : bk;
    const float* W1s  = isQ ? W1 : (W1 + DMSG * DFF);
    float* A          = isQ ? (g_Aq + bn * DFF) : (g_Ak + bn * DFF);

    __shared__ float s_inv[DINV];
    __shared__ float s_part[4][DMSG];
    __shared__ float s_msg[DMSG];

    int tid = threadIdx.x;
    s_inv[tid] = inv[tid];
    __syncthreads();

    int m = tid & 63, g = tid >> 6;
    float acc = 0.f;
    #pragma unroll 16
    for (int i = g * 64; i < g * 64 + 64; i++)
        acc = fmaf(s_inv[i], W[i * DMSG + m], acc);
    s_part[g][m] = acc;
    __syncthreads();
    if (tid < DMSG)
        s_msg[tid] = s_part[0][tid] + s_part[1][tid] + s_part[2][tid] + s_part[3][tid] + bias[tid];
    __syncthreads();

    float a = isQ ? b1[tid] : 0.f;
    #pragma unroll 32
    for (int mm = 0; mm < DMSG; mm++)
        a = fmaf(s_msg[mm], W1s[mm * DFF + tid], a);
    A[tid] = a;
}

// ---------------- persistent pairwise kernel (weights resident) ----------------
__global__ void __launch_bounds__(256, 1) pair_kernel(
    const float* __restrict__ q_equi, const float* __restrict__ k_equi,
    const float* __restrict__ b2, float* __restrict__ out)
{
    extern __shared__ char smem[];
    const uint32_t sb = smem_u32(smem);
    int tid = threadIdx.x;
    int w = tid >> 5, lane = tid & 31;

    __half* sA  = (__half*)(smem + OFF_SA);
    float*  sAq = (float*)(smem + OFF_AQ);
    float*  sAk = (float*)(smem + OFF_AK);
    __half* sH  = (__half*)(smem + OFF_H);
    float*  sb2 = (float*)(smem + OFF_B2);

    // ---- one-time: stage full W1T, W2T, b2 ----
    {
        const float4* s1 = (const float4*)g_W1T;
        float4* d1 = (float4*)(smem + OFF_W1);
        for (int i = tid; i < (DFF * LDA * 2) / 16; i += 256) d1[i] = s1[i];
        const float4* s2 = (const float4*)g_W2T;
        float4* d2 = (float4*)(smem + OFF_W2);
        for (int i = tid; i < (DOUT * LDW2 * 2) / 16; i += 256) d2[i] = s2[i];
        if (tid < 64) sb2[tid] = b2[tid];
    }

    // ---- ldmatrix lane address bases ----
    const int m0 = w * 16;
    const uint32_t aAddr1 = sb + OFF_SA + ((m0 + (lane & 15)) * LDA + (lane >> 4) * 8) * 2;
    const uint32_t aAddr2 = sb + OFF_H  + ((m0 + (lane & 15)) * LDH + (lane >> 4) * 8) * 2;
    const int bRow = (lane & 7) + ((lane >> 4) << 3);
    const uint32_t bAddr1 = sb + OFF_W1 + (bRow * LDA  + ((lane >> 3) & 1) * 8) * 2;
    const uint32_t bAddr2 = sb + OFF_W2 + (bRow * LDW2 + ((lane >> 3) & 1) * 8) * 2;

    const int r = lane >> 2, cp = (lane & 3) * 2;
    const int m_lo = m0 + r, m_hi = m0 + r + 8;
    const int qi_lo = m_lo >> 3, ki_lo = m_lo & 7;
    const int qi_hi = m_hi >> 3, ki_hi = m_hi & 7;

    float* sqe = (float*)(smem + OFF_H);           // equi staging aliases sH
    float* ske = sqe + TQ * 192;

    // ================= persistent tile loop =================
    for (int t = blockIdx.x; t < NTILES; t += gridDim.x) {
        int b  = t / ((NQ / TQ) * (NK / TK));
        int rr = t % ((NQ / TQ) * (NK / TK));
        int q0 = (rr / (NK / TK)) * TQ;
        int k0 = (rr % (NK / TK)) * TK;

        __syncthreads();   // protect sH/sA/sAq/sAk from previous tile's readers

        // ---- stage equi (into sH alias) + Aq/Ak ----
        {
            const float4* q4 = (const float4*)(q_equi + (size_t)(b * NQ + q0) * 192);
            const float4* k4 = (const float4*)(k_equi + (size_t)(b * NK + k0) * 192);
            for (int i = tid; i < TQ * 48; i += 256) ((float4*)sqe)[i] = q4[i];
            for (int i = tid; i < TK * 48; i += 256) ((float4*)ske)[i] = k4[i];
            const float4* aq4 = (const float4*)(g_Aq + (size_t)(b * NQ + q0) * DFF);
            const float4* ak4 = (const float4*)(g_Ak + (size_t)(b * NK + k0) * DFF);
            for (int i = tid; i < TQ * 64; i += 256) {
                int row = i >> 6, c4 = i & 63;
                *(float4*)(sAq + row * LDAQ + c4 * 4) = aq4[i];
            }
            for (int i = tid; i < TK * 64; i += 256) {
                int row = i >> 6, c4 = i & 63;
                *(float4*)(sAk + row * LDAQ + c4 * 4) = ak4[i];
            }
        }
        __syncthreads();

        // ---- dot & dist -> sA fp16 [128][LDA] ----
        for (int idx = tid; idx < TM * 32; idx += 256) {
            int p = idx >> 5, e2 = (idx & 31) * 2;
            int qi = p >> 3, ki = p & 7;
            const float* qr = sqe + qi * 192 + e2;
            const float* kr = ske + ki * 192 + e2;
            float2 a0 = *(const float2*)(qr);
            float2 a1 = *(const float2*)(qr + 64);
            float2 a2 = *(const float2*)(qr + 128);
            float2 g0 = *(const float2*)(kr);
            float2 g1 = *(const float2*)(kr + 64);
            float2 g2 = *(const float2*)(kr + 128);
            float dx = a0.x * g0.x + a1.x * g1.x + a2.x * g2.x;
            float dy = a0.y * g0.y + a1.y * g1.y + a2.y * g2.y;
            float fx0 = a0.x - g0.x, fx1 = a1.x - g1.x, fx2 = a2.x - g2.x;
            float fy0 = a0.y - g0.y, fy1 = a1.y - g1.y, fy2 = a2.y - g2.y;
            float sx = sqrtf(fx0 * fx0 + fx1 * fx1 + fx2 * fx2);
            float sy = sqrtf(fy0 * fy0 + fy1 * fy1 + fy2 * fy2);
            *(__half2*)(sA + p * LDA + e2)      = __floats2half2_rn(dx, dy);
            *(__half2*)(sA + p * LDA + 64 + e2) = __floats2half2_rn(sx, sy);
        }
        __syncthreads();   // sA ready; equi staging dead (sH now free for h)

        float acc2[8][4];
        #pragma unroll
        for (int j = 0; j < 8; j++)
            #pragma unroll
            for (int i = 0; i < 4; i++) acc2[j][i] = 0.f;

        // ---- chunk loop over N (4 x 64): NO block barriers inside ----
        for (int c = 0; c < 4; c++) {
            float acc1[8][4];
            #pragma unroll
            for (int j = 0; j < 8; j++)
                #pragma unroll
                for (int i = 0; i < 4; i++) acc1[j][i] = 0.f;

            // GEMM1 chunk: acc1[16,64] = A[16,128] @ W1[c*64:(c+1)*64, :]^T
            const uint32_t bA1 = bAddr1 + c * 64 * LDA * 2;
            #pragma unroll
            for (int kk = 0; kk < 8; kk++) {
                uint32_t a0, a1, a2, a3;
                ldsm4(a0, a1, a2, a3, aAddr1 + kk * 32);
                #pragma unroll
                for (int jp = 0; jp < 4; jp++) {
                    uint32_t b0, b1, b2r, b3;
                    ldsm4(b0, b1, b2r, b3, bA1 + jp * 16 * LDA * 2 + kk * 32);
                    mma16816(acc1[2 * jp],     a0, a1, a2, a3, b0,  b1);
                    mma16816(acc1[2 * jp + 1], a0, a1, a2, a3, b2r, b3);
                }
            }

            // epilogue1: + Aq + Ak, SiLU, -> sH fp16 (warp-private rows)
            {
                const float* aqlo = sAq + qi_lo * LDAQ + c * 64;
                const float* aklo = sAk + ki_lo * LDAQ + c * 64;
                const float* aqhi = sAq + qi_hi * LDAQ + c * 64;
                const float* akhi = sAk + ki_hi * LDAQ + c * 64;
                #pragma unroll
                for (int j = 0; j < 8; j++) {
                    int n = j * 8 + cp;
                    float v0 = acc1[j][0] + aqlo[n]     + aklo[n];
                    float v1 = acc1[j][1] + aqlo[n + 1] + aklo[n + 1];
                    float v2 = acc1[j][2] + aqhi[n]     + akhi[n];
                    float v3 = acc1[j][3] + aqhi[n + 1] + akhi[n + 1];
                    *(__half2*)(sH + m_lo * LDH + n) = __floats2half2_rn(silu_f(v0), silu_f(v1));
                    *(__half2*)(sH + m_hi * LDH + n) = __floats2half2_rn(silu_f(v2), silu_f(v3));
                }
            }
            __syncwarp();   // warp's GEMM2 A-frags come only from its own rows

            // GEMM2 partial: acc2 += h[16,64] @ W2[:, c*64:(c+1)*64]^T
            const uint32_t bA2 = bAddr2 + c * 64 * 2;
            #pragma unroll
            for (int kk = 0; kk < 4; kk++) {
                uint32_t a0, a1, a2, a3;
                ldsm4(a0, a1, a2, a3, aAddr2 + kk * 32);
                #pragma unroll
                for (int jp = 0; jp < 4; jp++) {
                    uint32_t b0, b1, b2r, b3;
                    ldsm4(b0, b1, b2r, b3, bA2 + jp * 16 * LDW2 * 2 + kk * 32);
                    mma16816(acc2[2 * jp],     a0, a1, a2, a3, b0,  b1);
                    mma16816(acc2[2 * jp + 1], a0, a1, a2, a3, b2r, b3);
                }
            }
            __syncwarp();   // sH rows reused next chunk (warp-private)
        }

        // ---- epilogue2: + b2, store ----
        {
            float* olo = out + ((size_t)(b * NQ + q0 + qi_lo) * NK + (k0 + ki_lo)) * DOUT;
            float* ohi = out + ((size_t)(b * NQ + q0 + qi_hi) * NK + (k0 + ki_hi)) * DOUT;
            #pragma unroll
            for (int j = 0; j < 8; j++) {
                int n = j * 8 + cp;
                float2 v0, v1;
                v0.x = acc2[j][0] + sb2[n];
                v0.y = acc2[j][1] + sb2[n + 1];
                v1.x = acc2[j][2] + sb2[n];
                v1.y = acc2[j][3] + sb2[n + 1];
                *(float2*)(olo + n) = v0;
                *(float2*)(ohi + n) = v1;
            }
        }
    }
}

// ---------------------------------------------------------------------------
extern "C" void kernel_launch(void* const* d_in, const int* in_sizes, int n_in,
                              void* d_out, int out_size)
{
    const float* q_equi = (const float*)d_in[0];
    const float* q_inv  = (const float*)d_in[1];
    const float* k_equi = (const float*)d_in[2];
    const float* k_inv  = (const float*)d_in[3];
    const float* Wq     = (const float*)d_in[4];
    const float* bq     = (const float*)d_in[5];
    const float* Wk     = (const float*)d_in[6];
    const float* bk     = (const float*)d_in[7];
    const float* W1     = (const float*)d_in[8];
    const float* b1     = (const float*)d_in[9];
    const float* W2     = (const float*)d_in[10];
    const float* b2     = (const float*)d_in[11];
    float* out = (float*)d_out;

    cudaFuncSetAttribute(pair_kernel, cudaFuncAttributeMaxDynamicSharedMemorySize, SMEM_BYTES);

    prelude_kernel<<<NPRE + NPREP, 256>>>(q_inv, k_inv, Wq, bq, Wk, bk, W1, b1, W2);

    pair_kernel<<<148, 256, SMEM_BYTES>>>(q_equi, k_equi, b2, out);
}

// round 6
// speedup vs baseline: 1.8582x; 1.8582x over previous
#include <cuda_runtime.h>
#include <cuda_fp16.h>
#include <cstdint>

// ---------------- problem constants ----------------
#define BB    4
#define NQ    384
#define NK    384
#define DE    64
#define DMSG  64
#define DFF   256
#define DOUT  64
#define DINV  256

#define TQ    16
#define TK    8
#define TM    128          // pairs per tile

#define LDA   136          // half pitch for A / W1 chunk tiles (k=128 + 8 pad)
#define LDH   72           // half pitch for h / W2 chunk tiles (k=64 + 8 pad)
#define LDAQ  260          // float pitch for sAq/sAk (bank-conflict-free)

#define NPRE  (BB * (NQ + NK))   // 3072 prelude blocks
#define NPREP 96                 // weight-prep blocks appended

// ---------------- device scratch ----------------
__device__ float g_Aq[BB * NQ * DFF];
__device__ float g_Ak[BB * NK * DFF];
__device__ __align__(16) __half g_W1T[DFF * LDA];   // [n=256][k pitch 136] fp16
__device__ __align__(16) __half g_W2T[DOUT * 264];  // [n=64][k pitch 264] fp16

// ---------------- SMEM map (bytes) ----------------
#define OFF_SA   0        // 128*136*2 = 34816   A (dot|dist) fp16
#define OFF_AQ   34816    // 16*260*4  = 16640   A_q fp32 (padded pitch)
#define OFF_AK   51456    //  8*260*4  =  8320   A_k fp32 (padded pitch)
#define OFF_W1C  59776    // 64*136*2  = 17408   W1T chunk (aliased: qe staging)
#define OFF_H    77184    // 128*72*2  = 18432   h chunk fp16 (aliased: ke staging)
#define OFF_W2C  95616    // 64*72*2   =  9216   W2T chunk
#define OFF_B2   104832   // 64*4      =   256
#define SMEM_BYTES 105088

__device__ __forceinline__ uint32_t smem_u32(const void* p) {
    uint32_t a;
    asm("{ .reg .u64 t; cvta.to.shared.u64 t, %1; cvt.u32.u64 %0, t; }" : "=r"(a) : "l"(p));
    return a;
}
__device__ __forceinline__ void ldsm4(uint32_t& r0, uint32_t& r1, uint32_t& r2, uint32_t& r3,
                                      uint32_t addr) {
    asm volatile("ldmatrix.sync.aligned.m8n8.x4.shared.b16 {%0,%1,%2,%3}, [%4];"
        : "=r"(r0), "=r"(r1), "=r"(r2), "=r"(r3) : "r"(addr));
}
__device__ __forceinline__ void mma16816(float* c, uint32_t a0, uint32_t a1, uint32_t a2,
                                         uint32_t a3, uint32_t b0, uint32_t b1) {
    asm volatile(
        "mma.sync.aligned.m16n8k16.row.col.f32.f16.f16.f32 "
        "{%0,%1,%2,%3}, {%4,%5,%6,%7}, {%8,%9}, {%0,%1,%2,%3};"
        : "+f"(c[0]), "+f"(c[1]), "+f"(c[2]), "+f"(c[3])
        : "r"(a0), "r"(a1), "r"(a2), "r"(a3), "r"(b0), "r"(b1));
}
// silu on a half2: h = 0.5x + 0.5x * tanh(0.5x)  (1 MUFU per 2 values)
__device__ __forceinline__ uint32_t silu_h2(uint32_t xu) {
    uint32_t hxu, tu, res;
    asm("mul.rn.f16x2 %0, %1, %2;" : "=r"(hxu) : "r"(xu), "r"(0x38003800u)); // *0.5
    asm("tanh.approx.f16x2 %0, %1;" : "=r"(tu) : "r"(hxu));
    asm("fma.rn.f16x2 %0, %1, %2, %3;" : "=r"(res) : "r"(hxu), "r"(tu), "r"(hxu));
    return res;
}

// ---------------- prelude: A_q / A_k (+ appended weight-prep) ----------------
__global__ void __launch_bounds__(256) prelude_kernel(
    const float* __restrict__ q_inv, const float* __restrict__ k_inv,
    const float* __restrict__ Wq, const float* __restrict__ bq,
    const float* __restrict__ Wk, const float* __restrict__ bk,
    const float* __restrict__ W1, const float* __restrict__ b1,
    const float* __restrict__ W2)
{
    int blk = blockIdx.x;

    if (blk >= NPRE) {
        int idx = (blk - NPRE) * 256 + threadIdx.x;
        int total = DFF * 128 + DOUT * DFF;
        for (; idx < total; idx += NPREP * 256) {
            if (idx < DFF * 128) {
                int n = idx >> 7, k = idx & 127;              // W1T[n,k] = W1[128+k, n]
                g_W1T[n * LDA + k] = __float2half(W1[(128 + k) * DFF + n]);
            } else {
                int j = idx - DFF * 128;
                int n = j >> 8, k = j & 255;                  // W2T[n,k] = W2[k, n]
                g_W2T[n * 264 + k] = __float2half(W2[k * DOUT + n]);
            }
        }
        return;
    }

    bool isQ = blk < BB * NQ;
    int bn = isQ ? blk : blk - BB * NQ;

    const float* inv  = isQ ? (q_inv + bn * DINV) : (k_inv + bn * DINV);
    const float* W    = isQ ? Wq : Wk;
    const float* bias = isQ ? bq : bk;
    const float* W1s  = isQ ? W1 : (W1 + DMSG * DFF);
    float* A          = isQ ? (g_Aq + bn * DFF) : (g_Ak + bn * DFF);

    __shared__ float s_inv[DINV];
    __shared__ float s_part[4][DMSG];
    __shared__ float s_msg[DMSG];

    int tid = threadIdx.x;
    s_inv[tid] = inv[tid];
    __syncthreads();

    int m = tid & 63, g = tid >> 6;
    float acc = 0.f;
    #pragma unroll 16
    for (int i = g * 64; i < g * 64 + 64; i++)
        acc = fmaf(s_inv[i], W[i * DMSG + m], acc);
    s_part[g][m] = acc;
    __syncthreads();
    if (tid < DMSG)
        s_msg[tid] = s_part[0][tid] + s_part[1][tid] + s_part[2][tid] + s_part[3][tid] + bias[tid];
    __syncthreads();

    float a = isQ ? b1[tid] : 0.f;
    #pragma unroll 32
    for (int mm = 0; mm < DMSG; mm++)
        a = fmaf(s_msg[mm], W1s[mm * DFF + tid], a);
    A[tid] = a;
}

// ---------------- main pairwise kernel (2 CTAs/SM) ----------------
__global__ void __launch_bounds__(256, 2) pair_kernel(
    const float* __restrict__ q_equi, const float* __restrict__ k_equi,
    const float* __restrict__ b2, float* __restrict__ out)
{
    extern __shared__ char smem[];
    const uint32_t sb = smem_u32(smem);
    int tid = threadIdx.x;
    int w = tid >> 5, lane = tid & 31;

    int b  = blockIdx.z;
    int q0 = blockIdx.y * TQ;
    int k0 = blockIdx.x * TK;

    __half* sA   = (__half*)(smem + OFF_SA);
    float*  sAq  = (float*)(smem + OFF_AQ);
    float*  sAk  = (float*)(smem + OFF_AK);
    __half* sW1c = (__half*)(smem + OFF_W1C);
    __half* sH   = (__half*)(smem + OFF_H);
    __half* sW2c = (__half*)(smem + OFF_W2C);
    float*  sb2  = (float*)(smem + OFF_B2);

    // ---- phase 0: stage equi (alias W1C/H), Aq/Ak (padded pitch), b2 ----
    {
        float* sqe = (float*)(smem + OFF_W1C);   // 16*192 floats
        float* ske = (float*)(smem + OFF_H);     //  8*192 floats
        const float4* q4 = (const float4*)(q_equi + (size_t)(b * NQ + q0) * 192);
        const float4* k4 = (const float4*)(k_equi + (size_t)(b * NK + k0) * 192);
        for (int i = tid; i < TQ * 48; i += 256) ((float4*)sqe)[i] = q4[i];
        for (int i = tid; i < TK * 48; i += 256) ((float4*)ske)[i] = k4[i];
        const float4* aq4 = (const float4*)(g_Aq + (size_t)(b * NQ + q0) * DFF);
        const float4* ak4 = (const float4*)(g_Ak + (size_t)(b * NK + k0) * DFF);
        for (int i = tid; i < TQ * 64; i += 256) {
            int row = i >> 6, c4 = i & 63;
            *(float4*)(sAq + row * LDAQ + c4 * 4) = aq4[i];
        }
        for (int i = tid; i < TK * 64; i += 256) {
            int row = i >> 6, c4 = i & 63;
            *(float4*)(sAk + row * LDAQ + c4 * 4) = ak4[i];
        }
        if (tid < 64) sb2[tid] = b2[tid];
        __syncthreads();

        // ---- phase 1: dot & dist -> sA fp16 [128][LDA] ----
        // thread owns k-row p0 (constant) and e-channel pair e2; loops q-rows.
        {
            int p0 = tid >> 5, e2 = (tid & 31) * 2;
            const float* kr = ske + p0 * 192 + e2;
            float2 g0 = *(const float2*)(kr);
            float2 g1 = *(const float2*)(kr + 64);
            float2 g2 = *(const float2*)(kr + 128);
            #pragma unroll
            for (int n = 0; n < 16; n++) {
                int p = n * 8 + p0;                 // qi = n, ki = p0
                const float* qr = sqe + n * 192 + e2;
                float2 a0 = *(const float2*)(qr);
                float2 a1 = *(const float2*)(qr + 64);
                float2 a2 = *(const float2*)(qr + 128);
                float dx = a0.x * g0.x + a1.x * g1.x + a2.x * g2.x;
                float dy = a0.y * g0.y + a1.y * g1.y + a2.y * g2.y;
                float fx0 = a0.x - g0.x, fx1 = a1.x - g1.x, fx2 = a2.x - g2.x;
                float fy0 = a0.y - g0.y, fy1 = a1.y - g1.y, fy2 = a2.y - g2.y;
                float sx = sqrtf(fx0 * fx0 + fx1 * fx1 + fx2 * fx2);
                float sy = sqrtf(fy0 * fy0 + fy1 * fy1 + fy2 * fy2);
                *(__half2*)(sA + p * LDA + e2)      = __floats2half2_rn(dx, dy);
                *(__half2*)(sA + p * LDA + 64 + e2) = __floats2half2_rn(sx, sy);
            }
        }
    }
    __syncthreads();

    // ---- ldmatrix lane address bases ----
    const int m0 = w * 16;
    const uint32_t aAddr1 = sb + OFF_SA + ((m0 + (lane & 15)) * LDA + (lane >> 4) * 8) * 2;
    const uint32_t aAddr2 = sb + OFF_H  + ((m0 + (lane & 15)) * LDH + (lane >> 4) * 8) * 2;
    const int bRow = (lane & 7) + ((lane >> 4) << 3);
    const uint32_t bAddr1 = sb + OFF_W1C + (bRow * LDA + ((lane >> 3) & 1) * 8) * 2;
    const uint32_t bAddr2 = sb + OFF_W2C + (bRow * LDH + ((lane >> 3) & 1) * 8) * 2;

    const int r = lane >> 2, cp = (lane & 3) * 2;
    const int m_lo = m0 + r, m_hi = m0 + r + 8;
    const int qi_lo = m_lo >> 3, ki_lo = m_lo & 7;
    const int qi_hi = m_hi >> 3, ki_hi = m_hi & 7;

    float acc2[8][4];
    #pragma unroll
    for (int j = 0; j < 8; j++)
        #pragma unroll
        for (int i = 0; i < 4; i++) acc2[j][i] = 0.f;

    // ================= chunk loop over N (4 x 64) =================
    for (int c = 0; c < 4; c++) {
        // ---- stage W1 chunk + W2 chunk ----
        {
            const uint4* src = (const uint4*)(g_W1T + c * 64 * LDA);
            uint4* dst = (uint4*)sW1c;
            #pragma unroll
            for (int i = tid; i < 64 * LDA * 2 / 16; i += 256) dst[i] = src[i];
            for (int i = tid; i < 64 * 8; i += 256) {
                int row = i >> 3, seg = i & 7;
                *(uint4*)(sW2c + row * LDH + seg * 8) =
                    *(const uint4*)(g_W2T + row * 264 + c * 64 + seg * 8);
            }
        }
        __syncthreads();

        // ---- GEMM1 chunk: acc1[16,64] = A[16,128] @ W1c^T ----
        float acc1[8][4];
        #pragma unroll
        for (int j = 0; j < 8; j++)
            #pragma unroll
            for (int i = 0; i < 4; i++) acc1[j][i] = 0.f;

        #pragma unroll
        for (int kk = 0; kk < 8; kk++) {
            uint32_t a0, a1, a2, a3;
            ldsm4(a0, a1, a2, a3, aAddr1 + kk * 32);
            #pragma unroll
            for (int jp = 0; jp < 4; jp++) {
                uint32_t b0, b1, b2r, b3;
                ldsm4(b0, b1, b2r, b3, bAddr1 + jp * 16 * LDA * 2 + kk * 32);
                mma16816(acc1[2 * jp],     a0, a1, a2, a3, b0,  b1);
                mma16816(acc1[2 * jp + 1], a0, a1, a2, a3, b2r, b3);
            }
        }

        // ---- epilogue1: + Aq + Ak, SiLU (tanh.f16x2), -> sH fp16 ----
        {
            const float* aqlo = sAq + qi_lo * LDAQ + c * 64;
            const float* aklo = sAk + ki_lo * LDAQ + c * 64;
            const float* aqhi = sAq + qi_hi * LDAQ + c * 64;
            const float* akhi = sAk + ki_hi * LDAQ + c * 64;
            #pragma unroll
            for (int j = 0; j < 8; j++) {
                int n = j * 8 + cp;
                float2 aql = *(const float2*)(aqlo + n);
                float2 akl = *(const float2*)(aklo + n);
                float2 aqh = *(const float2*)(aqhi + n);
                float2 akh = *(const float2*)(akhi + n);
                float v0 = acc1[j][0] + aql.x + akl.x;
                float v1 = acc1[j][1] + aql.y + akl.y;
                float v2 = acc1[j][2] + aqh.x + akh.x;
                float v3 = acc1[j][3] + aqh.y + akh.y;
                __half2 x0 = __floats2half2_rn(v0, v1);
                __half2 x1 = __floats2half2_rn(v2, v3);
                *(uint32_t*)(sH + m_lo * LDH + n) = silu_h2(*(uint32_t*)&x0);
                *(uint32_t*)(sH + m_hi * LDH + n) = silu_h2(*(uint32_t*)&x1);
            }
        }
        __syncwarp();   // warp's GEMM2 A-frags come only from its own rows

        // ---- GEMM2 partial: acc2 += h[16,64] @ W2c^T ----
        #pragma unroll
        for (int kk = 0; kk < 4; kk++) {
            uint32_t a0, a1, a2, a3;
            ldsm4(a0, a1, a2, a3, aAddr2 + kk * 32);
            #pragma unroll
            for (int jp = 0; jp < 4; jp++) {
                uint32_t b0, b1, b2r, b3;
                ldsm4(b0, b1, b2r, b3, bAddr2 + jp * 16 * LDH * 2 + kk * 32);
                mma16816(acc2[2 * jp],     a0, a1, a2, a3, b0,  b1);
                mma16816(acc2[2 * jp + 1], a0, a1, a2, a3, b2r, b3);
            }
        }
        __syncthreads();   // before restaging W chunks
    }

    // ---- epilogue2: + b2, store ----
    {
        float* olo = out + ((size_t)(b * NQ + q0 + qi_lo) * NK + (k0 + ki_lo)) * DOUT;
        float* ohi = out + ((size_t)(b * NQ + q0 + qi_hi) * NK + (k0 + ki_hi)) * DOUT;
        #pragma unroll
        for (int j = 0; j < 8; j++) {
            int n = j * 8 + cp;
            float2 v0, v1;
            v0.x = acc2[j][0] + sb2[n];
            v0.y = acc2[j][1] + sb2[n + 1];
            v1.x = acc2[j][2] + sb2[n];
            v1.y = acc2[j][3] + sb2[n + 1];
            *(float2*)(olo + n) = v0;
            *(float2*)(ohi + n) = v1;
        }
    }
}

// ---------------------------------------------------------------------------
extern "C" void kernel_launch(void* const* d_in, const int* in_sizes, int n_in,
                              void* d_out, int out_size)
{
    const float* q_equi = (const float*)d_in[0];
    const float* q_inv  = (const float*)d_in[1];
    const float* k_equi = (const float*)d_in[2];
    const float* k_inv  = (const float*)d_in[3];
    const float* Wq     = (const float*)d_in[4];
    const float* bq     = (const float*)d_in[5];
    const float* Wk     = (const float*)d_in[6];
    const float* bk     = (const float*)d_in[7];
    const float* W1     = (const float*)d_in[8];
    const float* b1     = (const float*)d_in[9];
    const float* W2     = (const float*)d_in[10];
    const float* b2     = (const float*)d_in[11];
    float* out = (float*)d_out;

    cudaFuncSetAttribute(pair_kernel, cudaFuncAttributeMaxDynamicSharedMemorySize, SMEM_BYTES);

    prelude_kernel<<<NPRE + NPREP, 256>>>(q_inv, k_inv, Wq, bq, Wk, bk, W1, b1, W2);

    dim3 grid(NK / TK, NQ / TQ, BB);
    pair_kernel<<<grid, 256, SMEM_BYTES>>>(q_equi, k_equi, b2, out);
}

// round 7
// speedup vs baseline: 2.0894x; 1.1245x over previous
#include <cuda_runtime.h>
#include <cuda_fp16.h>
#include <cstdint>

// ---------------- problem constants ----------------
#define BB    4
#define NQ    384
#define NK    384
#define DE    64
#define DMSG  64
#define DFF   256
#define DOUT  64
#define DINV  256

#define TQ    16
#define TK    8
#define TM    128          // pairs per tile

#define LDA   136          // half pitch for A / W1 chunk tiles (k=128 + 8 pad)
#define LDH   72           // half pitch for W2 chunk tiles (k=64 + 8 pad)
#define LDAQ  260          // float pitch for sAq/sAk (bank-conflict-free)

#define NPRE  (BB * (NQ + NK))   // 3072 prelude blocks
#define NPREP 96                 // weight-prep blocks appended

// ---------------- device scratch ----------------
__device__ float g_Aq[BB * NQ * DFF];
__device__ float g_Ak[BB * NK * DFF];
__device__ __align__(16) __half g_W1T[DFF * LDA];   // [n=256][k pitch 136] fp16
__device__ __align__(16) __half g_W2T[DOUT * 264];  // [n=64][k pitch 264] fp16

// ---------------- SMEM map (bytes) ----------------
#define OFF_SA   0        // 128*136*2 = 34816   A (dot|dist) fp16
#define OFF_AQ   34816    // 16*260*4  = 16640   A_q fp32 (padded pitch)
#define OFF_AK   51456    //  8*260*4  =  8320   A_k fp32 (padded pitch)
#define OFF_W1C  59776    // 64*136*2  = 17408   W1T chunk (aliased: qe staging)
#define OFF_W2C  77184    // 64*72*2   =  9216   W2T chunk (aliased: ke staging)
#define OFF_B2   86400    // 64*4      =   256
#define SMEM_BYTES 86656

__device__ __forceinline__ uint32_t smem_u32(const void* p) {
    uint32_t a;
    asm("{ .reg .u64 t; cvta.to.shared.u64 t, %1; cvt.u32.u64 %0, t; }" : "=r"(a) : "l"(p));
    return a;
}
__device__ __forceinline__ void ldsm4(uint32_t& r0, uint32_t& r1, uint32_t& r2, uint32_t& r3,
                                      uint32_t addr) {
    asm volatile("ldmatrix.sync.aligned.m8n8.x4.shared.b16 {%0,%1,%2,%3}, [%4];"
        : "=r"(r0), "=r"(r1), "=r"(r2), "=r"(r3) : "r"(addr));
}
__device__ __forceinline__ void mma16816(float* c, uint32_t a0, uint32_t a1, uint32_t a2,
                                         uint32_t a3, uint32_t b0, uint32_t b1) {
    asm volatile(
        "mma.sync.aligned.m16n8k16.row.col.f32.f16.f16.f32 "
        "{%0,%1,%2,%3}, {%4,%5,%6,%7}, {%8,%9}, {%0,%1,%2,%3};"
        : "+f"(c[0]), "+f"(c[1]), "+f"(c[2]), "+f"(c[3])
        : "r"(a0), "r"(a1), "r"(a2), "r"(a3), "r"(b0), "r"(b1));
}
// silu on a half2: h = 0.5x + 0.5x * tanh(0.5x)  (1 MUFU per 2 values)
__device__ __forceinline__ uint32_t silu_h2(uint32_t xu) {
    uint32_t hxu, tu, res;
    asm("mul.rn.f16x2 %0, %1, %2;" : "=r"(hxu) : "r"(xu), "r"(0x38003800u)); // *0.5
    asm("tanh.approx.f16x2 %0, %1;" : "=r"(tu) : "r"(hxu));
    asm("fma.rn.f16x2 %0, %1, %2, %3;" : "=r"(res) : "r"(hxu), "r"(tu), "r"(hxu));
    return res;
}

// ---------------- prelude: A_q / A_k (+ appended weight-prep) ----------------
__global__ void __launch_bounds__(256) prelude_kernel(
    const float* __restrict__ q_inv, const float* __restrict__ k_inv,
    const float* __restrict__ Wq, const float* __restrict__ bq,
    const float* __restrict__ Wk, const float* __restrict__ bk,
    const float* __restrict__ W1, const float* __restrict__ b1,
    const float* __restrict__ W2)
{
    int blk = blockIdx.x;

    if (blk >= NPRE) {
        int idx = (blk - NPRE) * 256 + threadIdx.x;
        int total = DFF * 128 + DOUT * DFF;
        for (; idx < total; idx += NPREP * 256) {
            if (idx < DFF * 128) {
                int n = idx >> 7, k = idx & 127;              // W1T[n,k] = W1[128+k, n]
                g_W1T[n * LDA + k] = __float2half(W1[(128 + k) * DFF + n]);
            } else {
                int j = idx - DFF * 128;
                int n = j >> 8, k = j & 255;                  // W2T[n,k] = W2[k, n]
                g_W2T[n * 264 + k] = __float2half(W2[k * DOUT + n]);
            }
        }
        return;
    }

    bool isQ = blk < BB * NQ;
    int bn = isQ ? blk : blk - BB * NQ;

    const float* inv  = isQ ? (q_inv + bn * DINV) : (k_inv + bn * DINV);
    const float* W    = isQ ? Wq : Wk;
    const float* bias = isQ ? bq : bk;
    const float* W1s  = isQ ? W1 : (W1 + DMSG * DFF);
    float* A          = isQ ? (g_Aq + bn * DFF) : (g_Ak + bn * DFF);

    __shared__ float s_inv[DINV];
    __shared__ float s_part[4][DMSG];
    __shared__ float s_msg[DMSG];

    int tid = threadIdx.x;
    s_inv[tid] = inv[tid];
    __syncthreads();

    int m = tid & 63, g = tid >> 6;
    float acc = 0.f;
    #pragma unroll 16
    for (int i = g * 64; i < g * 64 + 64; i++)
        acc = fmaf(s_inv[i], W[i * DMSG + m], acc);
    s_part[g][m] = acc;
    __syncthreads();
    if (tid < DMSG)
        s_msg[tid] = s_part[0][tid] + s_part[1][tid] + s_part[2][tid] + s_part[3][tid] + bias[tid];
    __syncthreads();

    float a = isQ ? b1[tid] : 0.f;
    #pragma unroll 32
    for (int mm = 0; mm < DMSG; mm++)
        a = fmaf(s_msg[mm], W1s[mm * DFF + tid], a);
    A[tid] = a;
}

// ---------------- main pairwise kernel (2 CTAs/SM) ----------------
__global__ void __launch_bounds__(256, 2) pair_kernel(
    const float* __restrict__ q_equi, const float* __restrict__ k_equi,
    const float* __restrict__ b2, float* __restrict__ out)
{
    extern __shared__ char smem[];
    const uint32_t sb = smem_u32(smem);
    int tid = threadIdx.x;
    int w = tid >> 5, lane = tid & 31;

    int b  = blockIdx.z;
    int q0 = blockIdx.y * TQ;
    int k0 = blockIdx.x * TK;

    __half* sA   = (__half*)(smem + OFF_SA);
    float*  sAq  = (float*)(smem + OFF_AQ);
    float*  sAk  = (float*)(smem + OFF_AK);
    __half* sW1c = (__half*)(smem + OFF_W1C);
    __half* sW2c = (__half*)(smem + OFF_W2C);
    float*  sb2  = (float*)(smem + OFF_B2);

    // ---- phase 0: stage equi (alias W1C/W2C), Aq/Ak (padded pitch), b2 ----
    {
        float* sqe = (float*)(smem + OFF_W1C);   // 16*192 floats = 12288 B (< 17408)
        float* ske = (float*)(smem + OFF_W2C);   //  8*192 floats =  6144 B (<  9216)
        const float4* q4 = (const float4*)(q_equi + (size_t)(b * NQ + q0) * 192);
        const float4* k4 = (const float4*)(k_equi + (size_t)(b * NK + k0) * 192);
        for (int i = tid; i < TQ * 48; i += 256) ((float4*)sqe)[i] = q4[i];
        for (int i = tid; i < TK * 48; i += 256) ((float4*)ske)[i] = k4[i];
        const float4* aq4 = (const float4*)(g_Aq + (size_t)(b * NQ + q0) * DFF);
        const float4* ak4 = (const float4*)(g_Ak + (size_t)(b * NK + k0) * DFF);
        for (int i = tid; i < TQ * 64; i += 256) {
            int row = i >> 6, c4 = i & 63;
            *(float4*)(sAq + row * LDAQ + c4 * 4) = aq4[i];
        }
        for (int i = tid; i < TK * 64; i += 256) {
            int row = i >> 6, c4 = i & 63;
            *(float4*)(sAk + row * LDAQ + c4 * 4) = ak4[i];
        }
        if (tid < 64) sb2[tid] = b2[tid];
        __syncthreads();

        // ---- phase 1: dot & dist -> sA fp16 [128][LDA] ----
        // thread owns k-row p0 (constant) and e-channel pair e2; loops q-rows.
        {
            int p0 = tid >> 5, e2 = (tid & 31) * 2;
            const float* kr = ske + p0 * 192 + e2;
            float2 g0 = *(const float2*)(kr);
            float2 g1 = *(const float2*)(kr + 64);
            float2 g2 = *(const float2*)(kr + 128);
            #pragma unroll
            for (int n = 0; n < 16; n++) {
                int p = n * 8 + p0;                 // qi = n, ki = p0
                const float* qr = sqe + n * 192 + e2;
                float2 a0 = *(const float2*)(qr);
                float2 a1 = *(const float2*)(qr + 64);
                float2 a2 = *(const float2*)(qr + 128);
                float dx = a0.x * g0.x + a1.x * g1.x + a2.x * g2.x;
                float dy = a0.y * g0.y + a1.y * g1.y + a2.y * g2.y;
                float fx0 = a0.x - g0.x, fx1 = a1.x - g1.x, fx2 = a2.x - g2.x;
                float fy0 = a0.y - g0.y, fy1 = a1.y - g1.y, fy2 = a2.y - g2.y;
                float sx = sqrtf(fx0 * fx0 + fx1 * fx1 + fx2 * fx2);
                float sy = sqrtf(fy0 * fy0 + fy1 * fy1 + fy2 * fy2);
                *(__half2*)(sA + p * LDA + e2)      = __floats2half2_rn(dx, dy);
                *(__half2*)(sA + p * LDA + 64 + e2) = __floats2half2_rn(sx, sy);
            }
        }
    }
    __syncthreads();

    // ---- ldmatrix lane address bases ----
    const int m0 = w * 16;
    const uint32_t aAddr1 = sb + OFF_SA + ((m0 + (lane & 15)) * LDA + (lane >> 4) * 8) * 2;
    const int bRow = (lane & 7) + ((lane >> 4) << 3);
    const uint32_t bAddr1 = sb + OFF_W1C + (bRow * LDA + ((lane >> 3) & 1) * 8) * 2;
    const uint32_t bAddr2 = sb + OFF_W2C + (bRow * LDH + ((lane >> 3) & 1) * 8) * 2;

    const int r = lane >> 2, cp = (lane & 3) * 2;
    const int m_lo = m0 + r, m_hi = m0 + r + 8;
    const int qi_lo = m_lo >> 3, ki_lo = m_lo & 7;
    const int qi_hi = m_hi >> 3, ki_hi = m_hi & 7;

    // ---- hoisted GEMM1 A-fragments (chunk-invariant): 8 x ldsm4 = 32 regs ----
    uint32_t af[8][4];
    #pragma unroll
    for (int kk = 0; kk < 8; kk++)
        ldsm4(af[kk][0], af[kk][1], af[kk][2], af[kk][3], aAddr1 + kk * 32);

    float acc2[8][4];
    #pragma unroll
    for (int j = 0; j < 8; j++)
        #pragma unroll
        for (int i = 0; i < 4; i++) acc2[j][i] = 0.f;

    // ================= chunk loop over N (4 x 64) =================
    for (int c = 0; c < 4; c++) {
        // ---- stage W1 chunk + W2 chunk ----
        {
            const uint4* src = (const uint4*)(g_W1T + c * 64 * LDA);
            uint4* dst = (uint4*)sW1c;
            #pragma unroll
            for (int i = tid; i < 64 * LDA * 2 / 16; i += 256) dst[i] = src[i];
            for (int i = tid; i < 64 * 8; i += 256) {
                int row = i >> 3, seg = i & 7;
                *(uint4*)(sW2c + row * LDH + seg * 8) =
                    *(const uint4*)(g_W2T + row * 264 + c * 64 + seg * 8);
            }
        }
        __syncthreads();

        // ---- GEMM1 chunk: acc1[16,64] = A[16,128] @ W1c^T ----
        float acc1[8][4];
        #pragma unroll
        for (int j = 0; j < 8; j++)
            #pragma unroll
            for (int i = 0; i < 4; i++) acc1[j][i] = 0.f;

        #pragma unroll
        for (int kk = 0; kk < 8; kk++) {
            #pragma unroll
            for (int jp = 0; jp < 4; jp++) {
                uint32_t b0, b1, b2r, b3;
                ldsm4(b0, b1, b2r, b3, bAddr1 + jp * 16 * LDA * 2 + kk * 32);
                mma16816(acc1[2 * jp],     af[kk][0], af[kk][1], af[kk][2], af[kk][3], b0,  b1);
                mma16816(acc1[2 * jp + 1], af[kk][0], af[kk][1], af[kk][2], af[kk][3], b2r, b3);
            }
        }

        // ---- epilogue1: + Aq + Ak, SiLU -> register h fragments (no smem) ----
        uint32_t hlo[8], hhi[8];
        {
            const float* aqlo = sAq + qi_lo * LDAQ + c * 64;
            const float* aklo = sAk + ki_lo * LDAQ + c * 64;
            const float* aqhi = sAq + qi_hi * LDAQ + c * 64;
            const float* akhi = sAk + ki_hi * LDAQ + c * 64;
            #pragma unroll
            for (int j = 0; j < 8; j++) {
                int n = j * 8 + cp;
                float2 aql = *(const float2*)(aqlo + n);
                float2 akl = *(const float2*)(aklo + n);
                float2 aqh = *(const float2*)(aqhi + n);
                float2 akh = *(const float2*)(akhi + n);
                float v0 = acc1[j][0] + aql.x + akl.x;
                float v1 = acc1[j][1] + aql.y + akl.y;
                float v2 = acc1[j][2] + aqh.x + akh.x;
                float v3 = acc1[j][3] + aqh.y + akh.y;
                __half2 x0 = __floats2half2_rn(v0, v1);
                __half2 x1 = __floats2half2_rn(v2, v3);
                hlo[j] = silu_h2(*(uint32_t*)&x0);
                hhi[j] = silu_h2(*(uint32_t*)&x1);
            }
        }

        // ---- GEMM2 partial: acc2 += h[16,64] @ W2c^T ----
        // register h fragments: kk-th k16 block A-frag = (hlo[2kk], hhi[2kk], hlo[2kk+1], hhi[2kk+1])
        #pragma unroll
        for (int kk = 0; kk < 4; kk++) {
            uint32_t a0 = hlo[2 * kk], a1 = hhi[2 * kk];
            uint32_t a2 = hlo[2 * kk + 1], a3 = hhi[2 * kk + 1];
            #pragma unroll
            for (int jp = 0; jp < 4; jp++) {
                uint32_t b0, b1, b2r, b3;
                ldsm4(b0, b1, b2r, b3, bAddr2 + jp * 16 * LDH * 2 + kk * 32);
                mma16816(acc2[2 * jp],     a0, a1, a2, a3, b0,  b1);
                mma16816(acc2[2 * jp + 1], a0, a1, a2, a3, b2r, b3);
            }
        }
        __syncthreads();   // before restaging W chunks
    }

    // ---- epilogue2: + b2, store ----
    {
        float* olo = out + ((size_t)(b * NQ + q0 + qi_lo) * NK + (k0 + ki_lo)) * DOUT;
        float* ohi = out + ((size_t)(b * NQ + q0 + qi_hi) * NK + (k0 + ki_hi)) * DOUT;
        #pragma unroll
        for (int j = 0; j < 8; j++) {
            int n = j * 8 + cp;
            float2 v0, v1;
            v0.x = acc2[j][0] + sb2[n];
            v0.y = acc2[j][1] + sb2[n + 1];
            v1.x = acc2[j][2] + sb2[n];
            v1.y = acc2[j][3] + sb2[n + 1];
            *(float2*)(olo + n) = v0;
            *(float2*)(ohi + n) = v1;
        }
    }
}

// ---------------------------------------------------------------------------
extern "C" void kernel_launch(void* const* d_in, const int* in_sizes, int n_in,
                              void* d_out, int out_size)
{
    const float* q_equi = (const float*)d_in[0];
    const float* q_inv  = (const float*)d_in[1];
    const float* k_equi = (const float*)d_in[2];
    const float* k_inv  = (const float*)d_in[3];
    const float* Wq     = (const float*)d_in[4];
    const float* bq     = (const float*)d_in[5];
    const float* Wk     = (const float*)d_in[6];
    const float* bk     = (const float*)d_in[7];
    const float* W1     = (const float*)d_in[8];
    const float* b1     = (const float*)d_in[9];
    const float* W2     = (const float*)d_in[10];
    const float* b2     = (const float*)d_in[11];
    float* out = (float*)d_out;

    cudaFuncSetAttribute(pair_kernel, cudaFuncAttributeMaxDynamicSharedMemorySize, SMEM_BYTES);

    prelude_kernel<<<NPRE + NPREP, 256>>>(q_inv, k_inv, Wq, bq, Wk, bk, W1, b1, W2);

    dim3 grid(NK / TK, NQ / TQ, BB);
    pair_kernel<<<grid, 256, SMEM_BYTES>>>(q_equi, k_equi, b2, out);
}

// round 8
// speedup vs baseline: 2.6749x; 1.2802x over previous
#include <cuda_runtime.h>
#include <cuda_fp16.h>
#include <cstdint>

// ---------------- problem constants ----------------
#define BB    4
#define NQ    384
#define NK    384
#define DE    64
#define DMSG  64
#define DFF   256
#define DOUT  64
#define DINV  256

#define TQ    16
#define TK    8
#define TM    128          // pairs per tile

#define LDA   136          // half pitch for A / W1 chunk tiles (k=128 + 8 pad)
#define LDH   72           // half pitch for W2 chunk tiles (k=64 + 8 pad)
#define LDAQ  260          // float pitch for sAq/sAk (bank-conflict-free)

#define NPRE  (BB * (NQ + NK))   // 3072 prelude blocks
#define NPREP 96                 // weight-prep blocks appended

// ---------------- device scratch ----------------
__device__ float g_Aq[BB * NQ * DFF];
__device__ float g_Ak[BB * NK * DFF];
__device__ __align__(16) __half g_W1T[DFF * LDA];   // [n=256][k pitch 136] fp16
__device__ __align__(16) __half g_W2T[DOUT * 264];  // [n=64][k pitch 264] fp16

// ---------------- SMEM map (bytes) ----------------
#define OFF_SA    0        // 128*136*2 = 34816
#define OFF_AQ    34816    // 16*260*4  = 16640
#define OFF_AK    51456    //  8*260*4  =  8320
#define OFF_W1C0  59776    // 17408
#define OFF_W2C0  77184    //  9216
#define OFF_W1C1  86400    // 17408   (aliased: equi staging, 18432 <= 26624)
#define OFF_W2C1  103808   //  9216
#define OFF_B2    113024   //   256
#define SMEM_BYTES 113280

__device__ __forceinline__ uint32_t smem_u32(const void* p) {
    uint32_t a;
    asm("{ .reg .u64 t; cvta.to.shared.u64 t, %1; cvt.u32.u64 %0, t; }" : "=r"(a) : "l"(p));
    return a;
}
#define CP_ASYNC16(dst, src) \
    asm volatile("cp.async.cg.shared.global [%0], [%1], 16;" :: "r"(dst), "l"(src))
#define CP_COMMIT() asm volatile("cp.async.commit_group;" ::: "memory")
#define CP_WAIT(n)  asm volatile("cp.async.wait_group %0;" :: "n"(n) : "memory")

__device__ __forceinline__ void ldsm4(uint32_t& r0, uint32_t& r1, uint32_t& r2, uint32_t& r3,
                                      uint32_t addr) {
    asm volatile("ldmatrix.sync.aligned.m8n8.x4.shared.b16 {%0,%1,%2,%3}, [%4];"
        : "=r"(r0), "=r"(r1), "=r"(r2), "=r"(r3) : "r"(addr));
}
__device__ __forceinline__ void mma16816(float* c, uint32_t a0, uint32_t a1, uint32_t a2,
                                         uint32_t a3, uint32_t b0, uint32_t b1) {
    asm volatile(
        "mma.sync.aligned.m16n8k16.row.col.f32.f16.f16.f32 "
        "{%0,%1,%2,%3}, {%4,%5,%6,%7}, {%8,%9}, {%0,%1,%2,%3};"
        : "+f"(c[0]), "+f"(c[1]), "+f"(c[2]), "+f"(c[3])
        : "r"(a0), "r"(a1), "r"(a2), "r"(a3), "r"(b0), "r"(b1));
}
// silu on a half2: h = 0.5x + 0.5x * tanh(0.5x)
__device__ __forceinline__ uint32_t silu_h2(uint32_t xu) {
    uint32_t hxu, tu, res;
    asm("mul.rn.f16x2 %0, %1, %2;" : "=r"(hxu) : "r"(xu), "r"(0x38003800u));
    asm("tanh.approx.f16x2 %0, %1;" : "=r"(tu) : "r"(hxu));
    asm("fma.rn.f16x2 %0, %1, %2, %3;" : "=r"(res) : "r"(hxu), "r"(tu), "r"(hxu));
    return res;
}

// ---------------- prelude: A_q / A_k (+ appended weight-prep) ----------------
__global__ void __launch_bounds__(256) prelude_kernel(
    const float* __restrict__ q_inv, const float* __restrict__ k_inv,
    const float* __restrict__ Wq, const float* __restrict__ bq,
    const float* __restrict__ Wk, const float* __restrict__ bk,
    const float* __restrict__ W1, const float* __restrict__ b1,
    const float* __restrict__ W2)
{
    int blk = blockIdx.x;

    if (blk >= NPRE) {
        int idx = (blk - NPRE) * 256 + threadIdx.x;
        int total = DFF * 128 + DOUT * DFF;
        for (; idx < total; idx += NPREP * 256) {
            if (idx < DFF * 128) {
                int n = idx >> 7, k = idx & 127;
                g_W1T[n * LDA + k] = __float2half(W1[(128 + k) * DFF + n]);
            } else {
                int j = idx - DFF * 128;
                int n = j >> 8, k = j & 255;
                g_W2T[n * 264 + k] = __float2half(W2[k * DOUT + n]);
            }
        }
        return;
    }

    bool isQ = blk < BB * NQ;
    int bn = isQ ? blk : blk - BB * NQ;

    const float* inv  = isQ ? (q_inv + bn * DINV) : (k_inv + bn * DINV);
    const float* W    = isQ ? Wq : Wk;
    const float* bias = isQ ? bq : bk;
    const float* W1s  = isQ ? W1 : (W1 + DMSG * DFF);
    float* A          = isQ ? (g_Aq + bn * DFF) : (g_Ak + bn * DFF);

    __shared__ float s_inv[DINV];
    __shared__ float s_part[4][DMSG];
    __shared__ float s_msg[DMSG];

    int tid = threadIdx.x;
    s_inv[tid] = inv[tid];
    __syncthreads();

    int m = tid & 63, g = tid >> 6;
    float acc = 0.f;
    #pragma unroll 16
    for (int i = g * 64; i < g * 64 + 64; i++)
        acc = fmaf(s_inv[i], W[i * DMSG + m], acc);
    s_part[g][m] = acc;
    __syncthreads();
    if (tid < DMSG)
        s_msg[tid] = s_part[0][tid] + s_part[1][tid] + s_part[2][tid] + s_part[3][tid] + bias[tid];
    __syncthreads();

    float a = isQ ? b1[tid] : 0.f;
    #pragma unroll 32
    for (int mm = 0; mm < DMSG; mm++)
        a = fmaf(s_msg[mm], W1s[mm * DFF + tid], a);
    A[tid] = a;
}

// ---------------- W chunk prefetch via cp.async ----------------
__device__ __forceinline__ void prefetch_w(int c, uint32_t w1dst, uint32_t w2dst, int tid) {
    const char* src1 = (const char*)(g_W1T + c * 64 * LDA);
    #pragma unroll
    for (int i = tid; i < 1088; i += 256)                 // 64*LDA*2/16
        CP_ASYNC16(w1dst + i * 16, src1 + i * 16);
    #pragma unroll
    for (int i = tid; i < 512; i += 256) {                // 64 rows * 8 segs
        int row = i >> 3, seg = i & 7;
        CP_ASYNC16(w2dst + (row * LDH + seg * 8) * 2,
                   (const char*)(g_W2T + row * 264 + c * 64 + seg * 8));
    }
}

// ---------------- main pairwise kernel (2 CTAs/SM) ----------------
__global__ void __launch_bounds__(256, 2) pair_kernel(
    const float* __restrict__ q_equi, const float* __restrict__ k_equi,
    const float* __restrict__ b2, float* __restrict__ out)
{
    extern __shared__ char smem[];
    const uint32_t sb = smem_u32(smem);
    int tid = threadIdx.x;
    int w = tid >> 5, lane = tid & 31;

    int b  = blockIdx.z;
    int q0 = blockIdx.y * TQ;
    int k0 = blockIdx.x * TK;

    __half* sA  = (__half*)(smem + OFF_SA);
    float*  sAq = (float*)(smem + OFF_AQ);
    float*  sAk = (float*)(smem + OFF_AK);
    float*  sb2 = (float*)(smem + OFF_B2);

    // ---- phase 0: async-stage equi (into buf1 alias), Aq/Ak, b2; prefetch W chunk0 ----
    {
        const uint32_t sqe_b = sb + OFF_W1C1;                 // 12288 B
        const uint32_t ske_b = sqe_b + TQ * 192 * 4;          //  6144 B
        const char* qsrc = (const char*)(q_equi + (size_t)(b * NQ + q0) * 192);
        const char* ksrc = (const char*)(k_equi + (size_t)(b * NK + k0) * 192);
        #pragma unroll
        for (int i = tid; i < 768; i += 256) CP_ASYNC16(sqe_b + i * 16, qsrc + i * 16);
        #pragma unroll
        for (int i = tid; i < 384; i += 256) CP_ASYNC16(ske_b + i * 16, ksrc + i * 16);
        const char* aqsrc = (const char*)(g_Aq + (size_t)(b * NQ + q0) * DFF);
        const char* aksrc = (const char*)(g_Ak + (size_t)(b * NK + k0) * DFF);
        #pragma unroll
        for (int i = tid; i < 1024; i += 256) {               // 16 rows * 64 float4
            int row = i >> 6, c4 = i & 63;
            CP_ASYNC16(sb + OFF_AQ + (row * LDAQ + c4 * 4) * 4, aqsrc + i * 16);
        }
        #pragma unroll
        for (int i = tid; i < 512; i += 256) {
            int row = i >> 6, c4 = i & 63;
            CP_ASYNC16(sb + OFF_AK + (row * LDAQ + c4 * 4) * 4, aksrc + i * 16);
        }
        if (tid < 16) CP_ASYNC16(sb + OFF_B2 + tid * 16, (const char*)b2 + tid * 16);
        CP_COMMIT();                                          // group: inputs

        prefetch_w(0, sb + OFF_W1C0, sb + OFF_W2C0, tid);
        CP_COMMIT();                                          // group: chunk 0

        CP_WAIT(1);                                           // inputs landed
        __syncthreads();
    }

    // ---- phase 1: dot & dist -> sA fp16 [128][LDA] ----
    {
        const float* sqe = (const float*)(smem + OFF_W1C1);
        const float* ske = sqe + TQ * 192;
        int p0 = tid >> 5, e2 = (tid & 31) * 2;
        const float* kr = ske + p0 * 192 + e2;
        float2 g0 = *(const float2*)(kr);
        float2 g1 = *(const float2*)(kr + 64);
        float2 g2 = *(const float2*)(kr + 128);
        #pragma unroll
        for (int n = 0; n < 16; n++) {
            int p = n * 8 + p0;                 // qi = n, ki = p0
            const float* qr = sqe + n * 192 + e2;
            float2 a0 = *(const float2*)(qr);
            float2 a1 = *(const float2*)(qr + 64);
            float2 a2 = *(const float2*)(qr + 128);
            float dx = a0.x * g0.x + a1.x * g1.x + a2.x * g2.x;
            float dy = a0.y * g0.y + a1.y * g1.y + a2.y * g2.y;
            float fx0 = a0.x - g0.x, fx1 = a1.x - g1.x, fx2 = a2.x - g2.x;
            float fy0 = a0.y - g0.y, fy1 = a1.y - g1.y, fy2 = a2.y - g2.y;
            float sx = sqrtf(fx0 * fx0 + fx1 * fx1 + fx2 * fx2);
            float sy = sqrtf(fy0 * fy0 + fy1 * fy1 + fy2 * fy2);
            *(__half2*)(sA + p * LDA + e2)      = __floats2half2_rn(dx, dy);
            *(__half2*)(sA + p * LDA + 64 + e2) = __floats2half2_rn(sx, sy);
        }
    }
    __syncthreads();   // sA ready; buf1 (equi) free for chunk-1 prefetch

    // ---- ldmatrix lane address bases ----
    const int m0 = w * 16;
    const uint32_t aAddr1 = sb + OFF_SA + ((m0 + (lane & 15)) * LDA + (lane >> 4) * 8) * 2;
    const int bRow = (lane & 7) + ((lane >> 4) << 3);
    const uint32_t bOff1 = (bRow * LDA + ((lane >> 3) & 1) * 8) * 2;
    const uint32_t bOff2 = (bRow * LDH + ((lane >> 3) & 1) * 8) * 2;
    const uint32_t b1Base[2] = { sb + OFF_W1C0 + bOff1, sb + OFF_W1C1 + bOff1 };
    const uint32_t b2Base[2] = { sb + OFF_W2C0 + bOff2, sb + OFF_W2C1 + bOff2 };
    const uint32_t w1Dst[2]  = { sb + OFF_W1C0, sb + OFF_W1C1 };
    const uint32_t w2Dst[2]  = { sb + OFF_W2C0, sb + OFF_W2C1 };

    const int r = lane >> 2, cp = (lane & 3) * 2;
    const int m_lo = m0 + r, m_hi = m0 + r + 8;
    const int qi_lo = m_lo >> 3, ki_lo = m_lo & 7;
    const int qi_hi = m_hi >> 3, ki_hi = m_hi & 7;

    // ---- hoisted GEMM1 A-fragments (chunk-invariant) ----
    uint32_t af[8][4];
    #pragma unroll
    for (int kk = 0; kk < 8; kk++)
        ldsm4(af[kk][0], af[kk][1], af[kk][2], af[kk][3], aAddr1 + kk * 32);

    float acc2[8][4];
    #pragma unroll
    for (int j = 0; j < 8; j++)
        #pragma unroll
        for (int i = 0; i < 4; i++) acc2[j][i] = 0.f;

    // ================= chunk loop over N (4 x 64), double-buffered =================
    for (int c = 0; c < 4; c++) {
        CP_WAIT(0);            // chunk c data resident
        __syncthreads();       // ...in every thread's view; also fences buffer reuse

        if (c < 3) {           // prefetch chunk c+1 into the other buffer
            prefetch_w(c + 1, w1Dst[(c + 1) & 1], w2Dst[(c + 1) & 1], tid);
            CP_COMMIT();
        }

        const uint32_t bA1 = b1Base[c & 1];
        const uint32_t bA2 = b2Base[c & 1];

        // ---- GEMM1 chunk: acc1[16,64] = A[16,128] @ W1c^T ----
        float acc1[8][4];
        #pragma unroll
        for (int j = 0; j < 8; j++)
            #pragma unroll
            for (int i = 0; i < 4; i++) acc1[j][i] = 0.f;

        #pragma unroll
        for (int kk = 0; kk < 8; kk++) {
            #pragma unroll
            for (int jp = 0; jp < 4; jp++) {
                uint32_t b0, b1r, b2r, b3;
                ldsm4(b0, b1r, b2r, b3, bA1 + jp * 16 * LDA * 2 + kk * 32);
                mma16816(acc1[2 * jp],     af[kk][0], af[kk][1], af[kk][2], af[kk][3], b0,  b1r);
                mma16816(acc1[2 * jp + 1], af[kk][0], af[kk][1], af[kk][2], af[kk][3], b2r, b3);
            }
        }

        // ---- epilogue1: + Aq + Ak, SiLU -> register h fragments ----
        uint32_t hlo[8], hhi[8];
        {
            const float* aqlo = sAq + qi_lo * LDAQ + c * 64;
            const float* aklo = sAk + ki_lo * LDAQ + c * 64;
            const float* aqhi = sAq + qi_hi * LDAQ + c * 64;
            const float* akhi = sAk + ki_hi * LDAQ + c * 64;
            #pragma unroll
            for (int j = 0; j < 8; j++) {
                int n = j * 8 + cp;
                float2 aql = *(const float2*)(aqlo + n);
                float2 akl = *(const float2*)(aklo + n);
                float2 aqh = *(const float2*)(aqhi + n);
                float2 akh = *(const float2*)(akhi + n);
                float v0 = acc1[j][0] + aql.x + akl.x;
                float v1 = acc1[j][1] + aql.y + akl.y;
                float v2 = acc1[j][2] + aqh.x + akh.x;
                float v3 = acc1[j][3] + aqh.y + akh.y;
                __half2 x0 = __floats2half2_rn(v0, v1);
                __half2 x1 = __floats2half2_rn(v2, v3);
                hlo[j] = silu_h2(*(uint32_t*)&x0);
                hhi[j] = silu_h2(*(uint32_t*)&x1);
            }
        }

        // ---- GEMM2 partial: acc2 += h[16,64] @ W2c^T (h stays in registers) ----
        #pragma unroll
        for (int kk = 0; kk < 4; kk++) {
            uint32_t a0 = hlo[2 * kk], a1 = hhi[2 * kk];
            uint32_t a2 = hlo[2 * kk + 1], a3 = hhi[2 * kk + 1];
            #pragma unroll
            for (int jp = 0; jp < 4; jp++) {
                uint32_t b0, b1r, b2r, b3;
                ldsm4(b0, b1r, b2r, b3, bA2 + jp * 16 * LDH * 2 + kk * 32);
                mma16816(acc2[2 * jp],     a0, a1, a2, a3, b0,  b1r);
                mma16816(acc2[2 * jp + 1], a0, a1, a2, a3, b2r, b3);
            }
        }
    }

    // ---- epilogue2: + b2, store ----
    {
        float* olo = out + ((size_t)(b * NQ + q0 + qi_lo) * NK + (k0 + ki_lo)) * DOUT;
        float* ohi = out + ((size_t)(b * NQ + q0 + qi_hi) * NK + (k0 + ki_hi)) * DOUT;
        #pragma unroll
        for (int j = 0; j < 8; j++) {
            int n = j * 8 + cp;
            float2 v0, v1;
            v0.x = acc2[j][0] + sb2[n];
            v0.y = acc2[j][1] + sb2[n + 1];
            v1.x = acc2[j][2] + sb2[n];
            v1.y = acc2[j][3] + sb2[n + 1];
            *(float2*)(olo + n) = v0;
            *(float2*)(ohi + n) = v1;
        }
    }
}

// ---------------------------------------------------------------------------
extern "C" void kernel_launch(void* const* d_in, const int* in_sizes, int n_in,
                              void* d_out, int out_size)
{
    const float* q_equi = (const float*)d_in[0];
    const float* q_inv  = (const float*)d_in[1];
    const float* k_equi = (const float*)d_in[2];
    const float* k_inv  = (const float*)d_in[3];
    const float* Wq     = (const float*)d_in[4];
    const float* bq     = (const float*)d_in[5];
    const float* Wk     = (const float*)d_in[6];
    const float* bk     = (const float*)d_in[7];
    const float* W1     = (const float*)d_in[8];
    const float* b1     = (const float*)d_in[9];
    const float* W2     = (const float*)d_in[10];
    const float* b2     = (const float*)d_in[11];
    float* out = (float*)d_out;

    cudaFuncSetAttribute(pair_kernel, cudaFuncAttributeMaxDynamicSharedMemorySize, SMEM_BYTES);

    prelude_kernel<<<NPRE + NPREP, 256>>>(q_inv, k_inv, Wq, bq, Wk, bk, W1, b1, W2);

    dim3 grid(NK / TK, NQ / TQ, BB);
    pair_kernel<<<grid, 256, SMEM_BYTES>>>(q_equi, k_equi, b2, out);
}